// round 4
// baseline (speedup 1.0000x reference)
#include <cuda_runtime.h>
#include <cuda_bf16.h>

#define BATCH   2
#define CH      256
#define FH      96
#define FW      96
#define FHW     (FH * FW)
#define POOLED  7
#define NBINS   (POOLED * POOLED)
#define N_ROIS  512
#define SPATIAL_SCALE 0.0625f
#define TRANS_STD     0.1f

#define CH_HALF 128
#define ROW_BYTES (FW * CH * 4)    // byte stride per feature row
#define COL_BYTES (CH * 4)         // byte stride per feature column

// NHWC scratch copy of the feature map: 2*96*96*256 floats = 18.9 MB (fits L2)
__device__ __align__(128) float g_feat_hwc[BATCH * FHW * CH];

// ---------------------------------------------------------------------------
// Transpose NCHW -> NHWC via 32x32 shared-memory tiles (coalesced both ways).
// ---------------------------------------------------------------------------
__global__ __launch_bounds__(256) void nchw_to_nhwc_kernel(const float* __restrict__ in) {
    __shared__ float tile[32][33];
    const int b   = blockIdx.z;
    const int hw0 = blockIdx.x * 32;
    const int c0  = blockIdx.y * 32;

    const float* src = in + (size_t)b * CH * FHW;
    #pragma unroll
    for (int j = 0; j < 32; j += 8) {
        int c  = c0 + threadIdx.y + j;
        int hw = hw0 + threadIdx.x;
        tile[threadIdx.y + j][threadIdx.x] = src[(size_t)c * FHW + hw];
    }
    __syncthreads();
    float* dst = g_feat_hwc + (size_t)b * FHW * CH;
    #pragma unroll
    for (int j = 0; j < 32; j += 8) {
        int hw = hw0 + threadIdx.y + j;
        int c  = c0 + threadIdx.x;
        dst[(size_t)hw * CH + c] = tile[threadIdx.x][threadIdx.y + j];
    }
}

// ---------------------------------------------------------------------------
// Deformable PS-RoI pooling, v4.
// Grid: (4, 512): blockIdx.x = half*2 + binhalf.  256 threads, warp = bin.
// Phase 1: 24/25 bins' coordinate data precomputed once into smem
//          (row/col byte offsets + coefficients, 1/count folded into ay).
// Phase 2: branch-free 4x4 weighted stencil, 16 independent LDG.128/thread.
// Phase 3: coalesced store of the staged [128ch x nb bins] tile.
// ---------------------------------------------------------------------------

template <int NB>
__device__ __forceinline__ void store_tile(float* __restrict__ o,
                                           const float* __restrict__ s_out,
                                           int tid)
{
    // o points at out[(n*CH + half*128)*49 + bh*24]; element (c, j) -> o[c*49 + j]
    #pragma unroll 4
    for (int i = tid; i < CH_HALF * NB; i += 256) {
        const int c = i / NB;
        const int j = i - c * NB;
        o[c * NBINS + j] = s_out[i];
    }
}

__global__ __launch_bounds__(256, 5) void dpsroi_pool_kernel(
    const float* __restrict__ rois,     // [N_ROIS, 5]
    const float* __restrict__ trans,    // [N_ROIS, 2, 7, 7]
    float* __restrict__ out)            // [N_ROIS, CH, 7, 7]
{
    __shared__ float s_out[CH_HALF * 25];     // 12.5 KB
    __shared__ int4   s_row[25];              // row byte offsets (4 corners)
    __shared__ int4   s_col[25];              // col byte offsets (4 corners)
    __shared__ float4 s_ax[25];               // x coefficients
    __shared__ float4 s_ay[25];               // y coefficients * inv(count)

    const int half = blockIdx.x >> 1;         // channel half
    const int bh   = blockIdx.x & 1;          // bin half: 0 -> bins 0..23, 1 -> 24..48
    const int n    = blockIdx.y;
    const int tid  = threadIdx.x;
    const int cg   = tid & 31;                // float4 channel group in half
    const int bsub = tid >> 5;                // warp id = bin sub-slot
    const int nb   = 24 + bh;                 // bins in this CTA
    const int bin0 = bh * 24;

    const float* roi = rois + n * 5;
    const int   bidx = (int)roi[0];

    // ---------------- Phase 1: per-bin coordinate setup ----------------
    if (tid < nb) {
        const float x1 = rintf(roi[1]) * SPATIAL_SCALE - 0.5f;
        const float y1 = rintf(roi[2]) * SPATIAL_SCALE - 0.5f;
        const float x2 = (rintf(roi[3]) + 1.0f) * SPATIAL_SCALE - 0.5f;
        const float y2 = (rintf(roi[4]) + 1.0f) * SPATIAL_SCALE - 0.5f;
        const float rw = fmaxf(x2 - x1, 0.1f);
        const float rh = fmaxf(y2 - y1, 0.1f);
        const float bin_w = rw * (1.0f / POOLED);
        const float bin_h = rh * (1.0f / POOLED);
        const float sub_w = bin_w * 0.5f;
        const float sub_h = bin_h * 0.5f;

        const int bin = bin0 + tid;
        const int ph = bin / POOLED;
        const int pw = bin % POOLED;

        const float tx = __ldg(trans + (size_t)n * 2 * NBINS + bin) * TRANS_STD;
        const float ty = __ldg(trans + (size_t)n * 2 * NBINS + NBINS + bin) * TRANS_STD;

        const float wstart = (float)pw * bin_w + x1 + tx * rw;
        const float hstart = (float)ph * bin_h + y1 + ty * rh;

        const float w0 = wstart, w1 = wstart + sub_w;
        const float h0 = hstart, h1 = hstart + sub_h;

        const float vx0 = (w0 >= -0.5f && w0 <= (float)FW - 0.5f) ? 1.0f : 0.0f;
        const float vx1 = (w1 >= -0.5f && w1 <= (float)FW - 0.5f) ? 1.0f : 0.0f;
        const float vy0 = (h0 >= -0.5f && h0 <= (float)FH - 0.5f) ? 1.0f : 0.0f;
        const float vy1 = (h1 >= -0.5f && h1 <= (float)FH - 0.5f) ? 1.0f : 0.0f;

        const float wc0 = fminf(fmaxf(w0, 0.0f), (float)FW - 1.0f);
        const float wc1 = fminf(fmaxf(w1, 0.0f), (float)FW - 1.0f);
        const float hc0 = fminf(fmaxf(h0, 0.0f), (float)FH - 1.0f);
        const float hc1 = fminf(fmaxf(h1, 0.0f), (float)FH - 1.0f);

        const float fx0 = floorf(wc0), fx1 = floorf(wc1);
        const float fy0 = floorf(hc0), fy1 = floorf(hc1);
        const float dx0 = wc0 - fx0, dx1 = wc1 - fx1;
        const float dy0 = hc0 - fy0, dy1 = hc1 - fy1;

        int4 col, row;
        col.x = (int)fx0 * COL_BYTES;
        col.y = (int)ceilf(wc0) * COL_BYTES;
        col.z = (int)fx1 * COL_BYTES;
        col.w = (int)ceilf(wc1) * COL_BYTES;
        row.x = (int)fy0 * ROW_BYTES;
        row.y = (int)ceilf(hc0) * ROW_BYTES;
        row.z = (int)fy1 * ROW_BYTES;
        row.w = (int)ceilf(hc1) * ROW_BYTES;

        const float count = (vx0 + vx1) * (vy0 + vy1);
        const float inv = (count > 0.0f) ? (1.0f / count) : 0.0f;

        float4 ax, ay;
        ax.x = vx0 * (1.0f - dx0);  ax.y = vx0 * dx0;
        ax.z = vx1 * (1.0f - dx1);  ax.w = vx1 * dx1;
        ay.x = vy0 * (1.0f - dy0) * inv;  ay.y = vy0 * dy0 * inv;
        ay.z = vy1 * (1.0f - dy1) * inv;  ay.w = vy1 * dy1 * inv;

        s_col[tid] = col;  s_row[tid] = row;
        s_ax[tid]  = ax;   s_ay[tid]  = ay;
    }
    __syncthreads();

    // ---------------- Phase 2: gather + weighted stencil ----------------
    const char* __restrict__ featb =
        (const char*)(g_feat_hwc + (size_t)bidx * FHW * CH + half * CH_HALF) + cg * 16;

    #pragma unroll 1
    for (int b0 = 0; b0 < 32; b0 += 8) {
        const int lb = b0 + bsub;
        if (lb < nb) {
            const int4   row = s_row[lb];
            const int4   col = s_col[lb];
            const float4 ax  = s_ax[lb];
            const float4 ay  = s_ay[lb];
            const int rowv[4] = {row.x, row.y, row.z, row.w};
            const int colv[4] = {col.x, col.y, col.z, col.w};
            const float axv[4] = {ax.x, ax.y, ax.z, ax.w};
            const float ayv[4] = {ay.x, ay.y, ay.z, ay.w};

            float4 acc = make_float4(0.f, 0.f, 0.f, 0.f);
            #pragma unroll
            for (int r = 0; r < 4; r++) {
                float4 rs = make_float4(0.f, 0.f, 0.f, 0.f);
                #pragma unroll
                for (int cc = 0; cc < 4; cc++) {
                    const float4 f = *(const float4*)(featb + (rowv[r] + colv[cc]));
                    rs.x += axv[cc] * f.x;
                    rs.y += axv[cc] * f.y;
                    rs.z += axv[cc] * f.z;
                    rs.w += axv[cc] * f.w;
                }
                acc.x += ayv[r] * rs.x;
                acc.y += ayv[r] * rs.y;
                acc.z += ayv[r] * rs.z;
                acc.w += ayv[r] * rs.w;
            }

            const int cbase = cg * 4;
            s_out[(cbase + 0) * nb + lb] = acc.x;
            s_out[(cbase + 1) * nb + lb] = acc.y;
            s_out[(cbase + 2) * nb + lb] = acc.z;
            s_out[(cbase + 3) * nb + lb] = acc.w;
        }
    }

    __syncthreads();

    // ---------------- Phase 3: coalesced output store ----------------
    float* o = out + ((size_t)n * CH + (size_t)half * CH_HALF) * NBINS + bin0;
    if (bh == 0) store_tile<24>(o, s_out, tid);
    else         store_tile<25>(o, s_out, tid);
}

extern "C" void kernel_launch(void* const* d_in, const int* in_sizes, int n_in,
                              void* d_out, int out_size)
{
    const float* bottom_data  = (const float*)d_in[0];  // (2,256,96,96)
    const float* bottom_rois  = (const float*)d_in[1];  // (512,5)
    const float* bottom_trans = (const float*)d_in[2];  // (512,2,7,7)
    float* out = (float*)d_out;                         // (512,256,7,7)

    {
        dim3 tb(32, 8);
        dim3 tg(FHW / 32, CH / 32, BATCH);
        nchw_to_nhwc_kernel<<<tg, tb>>>(bottom_data);
    }
    {
        dim3 pg(4, N_ROIS);
        dpsroi_pool_kernel<<<pg, 256>>>(bottom_rois, bottom_trans, out);
    }
}

// round 5
// speedup vs baseline: 1.3464x; 1.3464x over previous
#include <cuda_runtime.h>
#include <cuda_fp16.h>
#include <cuda_bf16.h>

#define BATCH   2
#define CH      256
#define FH      96
#define FW      96
#define FHW     (FH * FW)
#define POOLED  7
#define NBINS   (POOLED * POOLED)
#define N_ROIS  512
#define SPATIAL_SCALE 0.0625f
#define TRANS_STD     0.1f

#define CH_HALF 128
#define ROW_BYTES_H (FW * CH * 2)    // byte stride per feature row (half)
#define COL_BYTES_H (CH * 2)         // byte stride per feature column (half)

// NHWC fp16 scratch copy of the feature map: 2*96*96*256 halfs = 9.4 MB (L2-resident)
__device__ __align__(128) __half g_feat_h[BATCH * FHW * CH];

// ---------------------------------------------------------------------------
// Transpose NCHW f32 -> NHWC f16 via 32x32 shared tiles.
// Read coalesced f32; write half2 (32-bit stores, coalesced).
// ---------------------------------------------------------------------------
__global__ __launch_bounds__(256) void nchw_to_nhwc_half_kernel(const float* __restrict__ in) {
    __shared__ float tile[32][33];
    const int b   = blockIdx.z;
    const int hw0 = blockIdx.x * 32;
    const int c0  = blockIdx.y * 32;

    const float* src = in + (size_t)b * CH * FHW;
    #pragma unroll
    for (int j = 0; j < 32; j += 8) {
        tile[threadIdx.y + j][threadIdx.x] =
            src[(size_t)(c0 + threadIdx.y + j) * FHW + hw0 + threadIdx.x];
    }
    __syncthreads();

    const int lane = threadIdx.y * 32 + threadIdx.x;
    const int cp   = lane & 15;     // half2 column within the 32-channel tile
    const int hr   = lane >> 4;     // 0..15
    __half2* dst2 = (__half2*)g_feat_h + (size_t)b * FHW * (CH / 2);
    #pragma unroll
    for (int s = 0; s < 2; s++) {
        const int hl = hr + s * 16;
        const float a  = tile[2 * cp][hl];
        const float bv = tile[2 * cp + 1][hl];
        dst2[(size_t)(hw0 + hl) * (CH / 2) + (c0 >> 1) + cp] = __floats2half2_rn(a, bv);
    }
}

// ---------------------------------------------------------------------------
// Deformable PS-RoI pooling, v5 (fp16 gathers, conflict-free staging).
// Grid (4, 512): blockIdx.x = half*2 + binhalf. 256 threads, warp = bin.
// Branch-free separable 4x4 stencil; lanes load 4 half-channels (LDG.64).
// Results staged [bin][channel] via STS.128 (stride 33 float4 -> no conflicts),
// then one coalesced write per CTA.
// ---------------------------------------------------------------------------

template <int NB>
__device__ __forceinline__ void store_tile(float* __restrict__ o,
                                           const float* __restrict__ s_outf,
                                           int tid)
{
    #pragma unroll 4
    for (int i = tid; i < CH_HALF * NB; i += 256) {
        const int c = i / NB;
        const int j = i - c * NB;
        o[c * NBINS + j] = s_outf[j * 132 + c];
    }
}

__global__ __launch_bounds__(256, 5) void dpsroi_pool_kernel(
    const float* __restrict__ rois,     // [N_ROIS, 5]
    const float* __restrict__ trans,    // [N_ROIS, 2, 7, 7]
    float* __restrict__ out)            // [N_ROIS, CH, 7, 7]
{
    __shared__ float4 s_out4[25 * 33];        // [bin][33 float4] = 13.2 KB

    const int half = blockIdx.x >> 1;         // channel half
    const int bh   = blockIdx.x & 1;          // 0 -> bins 0..23, 1 -> bins 24..48
    const int n    = blockIdx.y;
    const int tid  = threadIdx.x;
    const int cg   = tid & 31;                // float4/half4 channel group
    const int bsub = tid >> 5;                // warp id
    const int nb   = 24 + bh;
    const int bin0 = bh * 24;

    const float* roi = rois + n * 5;
    const int   bidx = (int)roi[0];
    const float x1 = rintf(roi[1]) * SPATIAL_SCALE - 0.5f;
    const float y1 = rintf(roi[2]) * SPATIAL_SCALE - 0.5f;
    const float x2 = (rintf(roi[3]) + 1.0f) * SPATIAL_SCALE - 0.5f;
    const float y2 = (rintf(roi[4]) + 1.0f) * SPATIAL_SCALE - 0.5f;
    const float rw = fmaxf(x2 - x1, 0.1f);
    const float rh = fmaxf(y2 - y1, 0.1f);
    const float bin_w = rw * (1.0f / POOLED);
    const float bin_h = rh * (1.0f / POOLED);
    const float sub_w = bin_w * 0.5f;
    const float sub_h = bin_h * 0.5f;

    const char* __restrict__ featb =
        (const char*)(g_feat_h + (size_t)bidx * FHW * CH + half * CH_HALF) + cg * 8;

    const float* trans_n = trans + (size_t)n * 2 * NBINS;

    #pragma unroll 1
    for (int b0 = 0; b0 < 32; b0 += 8) {
        const int lb = b0 + bsub;
        if (lb < nb) {
            const int bin = bin0 + lb;
            const int ph = bin / POOLED;
            const int pw = bin % POOLED;

            const float tx = __ldg(trans_n + bin) * TRANS_STD;
            const float ty = __ldg(trans_n + NBINS + bin) * TRANS_STD;

            const float wstart = (float)pw * bin_w + x1 + tx * rw;
            const float hstart = (float)ph * bin_h + y1 + ty * rh;

            const float w0 = wstart, w1 = wstart + sub_w;
            const float h0 = hstart, h1 = hstart + sub_h;

            const float vx0 = (w0 >= -0.5f && w0 <= (float)FW - 0.5f) ? 1.0f : 0.0f;
            const float vx1 = (w1 >= -0.5f && w1 <= (float)FW - 0.5f) ? 1.0f : 0.0f;
            const float vy0 = (h0 >= -0.5f && h0 <= (float)FH - 0.5f) ? 1.0f : 0.0f;
            const float vy1 = (h1 >= -0.5f && h1 <= (float)FH - 0.5f) ? 1.0f : 0.0f;

            const float wc0 = fminf(fmaxf(w0, 0.0f), (float)FW - 1.0f);
            const float wc1 = fminf(fmaxf(w1, 0.0f), (float)FW - 1.0f);
            const float hc0 = fminf(fmaxf(h0, 0.0f), (float)FH - 1.0f);
            const float hc1 = fminf(fmaxf(h1, 0.0f), (float)FH - 1.0f);

            const float fx0 = floorf(wc0), fx1 = floorf(wc1);
            const float fy0 = floorf(hc0), fy1 = floorf(hc1);
            const float dx0 = wc0 - fx0, dx1 = wc1 - fx1;
            const float dy0 = hc0 - fy0, dy1 = hc1 - fy1;

            const int colv[4] = {
                (int)fx0 * COL_BYTES_H, (int)ceilf(wc0) * COL_BYTES_H,
                (int)fx1 * COL_BYTES_H, (int)ceilf(wc1) * COL_BYTES_H };
            const int rowv[4] = {
                (int)fy0 * ROW_BYTES_H, (int)ceilf(hc0) * ROW_BYTES_H,
                (int)fy1 * ROW_BYTES_H, (int)ceilf(hc1) * ROW_BYTES_H };

            const float count = (vx0 + vx1) * (vy0 + vy1);
            const float inv = (count > 0.0f) ? (1.0f / count) : 0.0f;

            const float axv[4] = { vx0 * (1.0f - dx0), vx0 * dx0,
                                   vx1 * (1.0f - dx1), vx1 * dx1 };
            const float ayv[4] = { vy0 * (1.0f - dy0) * inv, vy0 * dy0 * inv,
                                   vy1 * (1.0f - dy1) * inv, vy1 * dy1 * inv };

            float4 acc = make_float4(0.f, 0.f, 0.f, 0.f);
            #pragma unroll
            for (int r = 0; r < 4; r++) {
                float4 rs = make_float4(0.f, 0.f, 0.f, 0.f);
                #pragma unroll
                for (int cc = 0; cc < 4; cc++) {
                    const uint2 rv = *(const uint2*)(featb + (rowv[r] + colv[cc]));
                    const __half2 hlo = *(const __half2*)&rv.x;
                    const __half2 hhi = *(const __half2*)&rv.y;
                    const float2 lo = __half22float2(hlo);
                    const float2 hi = __half22float2(hhi);
                    rs.x += axv[cc] * lo.x;
                    rs.y += axv[cc] * lo.y;
                    rs.z += axv[cc] * hi.x;
                    rs.w += axv[cc] * hi.y;
                }
                acc.x += ayv[r] * rs.x;
                acc.y += ayv[r] * rs.y;
                acc.z += ayv[r] * rs.z;
                acc.w += ayv[r] * rs.w;
            }

            // conflict-free STS.128: [bin][cg], stride 33 float4
            s_out4[lb * 33 + cg] = acc;
        }
    }

    __syncthreads();

    float* o = out + ((size_t)n * CH + (size_t)half * CH_HALF) * NBINS + bin0;
    const float* s_outf = (const float*)s_out4;
    if (bh == 0) store_tile<24>(o, s_outf, tid);
    else         store_tile<25>(o, s_outf, tid);
}

extern "C" void kernel_launch(void* const* d_in, const int* in_sizes, int n_in,
                              void* d_out, int out_size)
{
    const float* bottom_data  = (const float*)d_in[0];  // (2,256,96,96)
    const float* bottom_rois  = (const float*)d_in[1];  // (512,5)
    const float* bottom_trans = (const float*)d_in[2];  // (512,2,7,7)
    float* out = (float*)d_out;                         // (512,256,7,7)

    {
        dim3 tb(32, 8);
        dim3 tg(FHW / 32, CH / 32, BATCH);
        nchw_to_nhwc_half_kernel<<<tg, tb>>>(bottom_data);
    }
    {
        dim3 pg(4, N_ROIS);
        dpsroi_pool_kernel<<<pg, 256>>>(bottom_rois, bottom_trans, out);
    }
}